// round 3
// baseline (speedup 1.0000x reference)
#include <cuda_runtime.h>

// ---------------------------------------------------------------------------
// MultiLoss_JSD: fused MSE + 17-head CE + histogram JSD
// B = 262144 rows; decoded/true: [B,168] f32; encoded: [B,11] f32; label: [B,1] f32
// out: 4 floats [multi, mse, ce, 0.1*kld]
// ---------------------------------------------------------------------------

#define NSLICE 17
#define NBINS  800
#define NCOLS  168
#define RATIO_JSD 0.1

// Compile-time column -> CE-slice classification.
// __host__ __device__ so nvcc accepts it in device constexpr context
// without --expt-relaxed-constexpr. Table lives inside the function body.
__host__ __device__ constexpr int slice_of(int c) {
    const int S[NSLICE][2] = {
        {1,10},{12,29},{30,33},{33,40},{40,64},{64,79},{79,84},{84,94},{94,96},
        {96,99},{99,105},{105,113},{116,122},{122,128},{128,151},{151,159},{160,165}};
    for (int i = 0; i < NSLICE; i++)
        if (c >= S[i][0] && c < S[i][1]) return i;
    return -1;  // MSE column
}

// ---------------- scratch (device globals; no allocation allowed) ----------
__device__ double   g_mse;
__device__ double   g_ce;
__device__ unsigned g_min[10];
__device__ unsigned g_max[10];
__device__ int      g_male;
__device__ int      g_hist[2][10][NBINS];   // [sex][dim][bin]

// ordered-uint encoding of float for atomicMin/Max
__device__ __forceinline__ unsigned f2o(float f) {
    unsigned u = __float_as_uint(f);
    return (u & 0x80000000u) ? ~u : (u | 0x80000000u);
}
__device__ __forceinline__ float o2f(unsigned u) {
    return (u & 0x80000000u) ? __uint_as_float(u & 0x7FFFFFFFu)
                             : __uint_as_float(~u);
}

// ---------------- init: zero scratch ---------------------------------------
__global__ void init_kernel() {
    int tid = blockIdx.x * blockDim.x + threadIdx.x;
    int total = 2 * 10 * NBINS;
    int* h = (int*)g_hist;
    for (int i = tid; i < total; i += gridDim.x * blockDim.x) h[i] = 0;
    if (tid < 10) { g_min[tid] = 0xFFFFFFFFu; g_max[tid] = 0u; }
    if (tid == 0) { g_mse = 0.0; g_ce = 0.0; g_male = 0; }
}

// ---------------- compile-time unrolled column handling --------------------
template <int C>
__device__ __forceinline__ void handle_col(float d, float t,
                                           float (&se)[NSLICE],
                                           float& dlab, float& msea) {
    constexpr int s = slice_of(C);
    if constexpr (s >= 0) {
        se[s] += __expf(d);
        dlab = __fmaf_rn(d, t, dlab);   // t is exact one-hot 0/1
    } else {
        float diff = d - t;
        msea = __fmaf_rn(diff, diff, msea);
    }
}

template <int I>
__device__ __forceinline__ void cols_loop(const float4* __restrict__ dp,
                                          const float4* __restrict__ tp,
                                          float (&se)[NSLICE],
                                          float& dlab, float& msea) {
    if constexpr (I < NCOLS / 4) {
        float4 d = __ldg(dp + I);
        float4 t = __ldg(tp + I);
        handle_col<4 * I + 0>(d.x, t.x, se, dlab, msea);
        handle_col<4 * I + 1>(d.y, t.y, se, dlab, msea);
        handle_col<4 * I + 2>(d.z, t.z, se, dlab, msea);
        handle_col<4 * I + 3>(d.w, t.w, se, dlab, msea);
        cols_loop<I + 1>(dp, tp, se, dlab, msea);
    }
}

// ---------------- main pass: MSE + CE + minmax + male count ----------------
__global__ void __launch_bounds__(256) main_kernel(
    const float* __restrict__ enc, const float* __restrict__ dec,
    const float* __restrict__ tru, const float* __restrict__ lab, int B) {

    __shared__ float    s_ce[8], s_mse[8];
    __shared__ unsigned s_mn[10], s_mx[10];
    __shared__ int      s_male;

    int tid = threadIdx.x;
    if (tid < 10) { s_mn[tid] = 0xFFFFFFFFu; s_mx[tid] = 0u; }
    if (tid == 0) s_male = 0;
    __syncthreads();

    int row = blockIdx.x * blockDim.x + tid;

    float ce_row = 0.0f, msea = 0.0f;
    float emn[10], emx[10];
    bool is_male = false;

    if (row < B) {
        float se[NSLICE];
#pragma unroll
        for (int i = 0; i < NSLICE; i++) se[i] = 0.0f;
        float dlab = 0.0f;

        const float4* dp = (const float4*)(dec + (size_t)row * NCOLS);
        const float4* tp = (const float4*)(tru + (size_t)row * NCOLS);
        cols_loop<0>(dp, tp, se, dlab, msea);

#pragma unroll
        for (int i = 0; i < NSLICE; i++) ce_row += __logf(se[i]);
        ce_row -= dlab;

        const float* ep = enc + (size_t)row * 11;
#pragma unroll
        for (int j = 0; j < 10; j++) {
            float v = __ldg(ep + j);
            emn[j] = v; emx[j] = v;
        }
        float lv = __ldg(lab + row);
        is_male = (lv < 0.5f);
    } else {
#pragma unroll
        for (int j = 0; j < 10; j++) {
            emn[j] = __int_as_float(0x7F800000);   // +inf
            emx[j] = __int_as_float(0xFF800000);   // -inf
        }
    }

    // warp reductions
    float cer = ce_row, mser = msea;
#pragma unroll
    for (int o = 16; o; o >>= 1) {
        cer  += __shfl_xor_sync(0xFFFFFFFFu, cer,  o);
        mser += __shfl_xor_sync(0xFFFFFFFFu, mser, o);
    }
#pragma unroll
    for (int j = 0; j < 10; j++) {
        float mn = emn[j], mx = emx[j];
#pragma unroll
        for (int o = 16; o; o >>= 1) {
            mn = fminf(mn, __shfl_xor_sync(0xFFFFFFFFu, mn, o));
            mx = fmaxf(mx, __shfl_xor_sync(0xFFFFFFFFu, mx, o));
        }
        emn[j] = mn; emx[j] = mx;
    }
    unsigned mb = __ballot_sync(0xFFFFFFFFu, is_male);

    int wid = tid >> 5;
    int lid = tid & 31;
    if (lid == 0) {
        s_ce[wid]  = cer;
        s_mse[wid] = mser;
#pragma unroll
        for (int j = 0; j < 10; j++) {
            atomicMin(&s_mn[j], f2o(emn[j]));
            atomicMax(&s_mx[j], f2o(emx[j]));
        }
        atomicAdd(&s_male, __popc(mb));
    }
    __syncthreads();

    if (tid == 0) {
        float c = 0.0f, m = 0.0f;
#pragma unroll
        for (int w = 0; w < 8; w++) { c += s_ce[w]; m += s_mse[w]; }
        atomicAdd(&g_ce,  (double)c);
        atomicAdd(&g_mse, (double)m);
        atomicAdd(&g_male, s_male);
    }
    if (tid < 10) {
        atomicMin(&g_min[tid], s_mn[tid]);
        atomicMax(&g_max[tid], s_mx[tid]);
    }
}

// ---------------- histogram pass (one sex per blockIdx.y) ------------------
__global__ void __launch_bounds__(256) hist_kernel(
    const float* __restrict__ enc, const float* __restrict__ lab, int B) {

    __shared__ int sh[10 * NBINS];   // 32 KB
    for (int i = threadIdx.x; i < 10 * NBINS; i += 256) sh[i] = 0;
    __syncthreads();

    int sex = blockIdx.y;   // 0 = male (label 0), 1 = female (label 1)

    float mnv[10], rng[10];
#pragma unroll
    for (int j = 0; j < 10; j++) {
        mnv[j] = o2f(g_min[j]);
        rng[j] = o2f(g_max[j]) - mnv[j];
    }

    int stride = gridDim.x * blockDim.x;
    for (int row = blockIdx.x * blockDim.x + threadIdx.x; row < B; row += stride) {
        float lv = __ldg(lab + row);
        int rsex = (lv < 0.5f) ? 0 : 1;
        if (rsex != sex) continue;
        const float* ep = enc + (size_t)row * 11;
#pragma unroll
        for (int j = 0; j < 10; j++) {
            float x = __ldg(ep + j);
            // match jax fp32: t = (x-mn)/(mx-mn); idx = clip(floor(t*800),0,799)
            float t  = __fdiv_rn(x - mnv[j], rng[j]);
            float ft = floorf(__fmul_rn(t, (float)NBINS));
            int idx = (int)ft;
            idx = max(0, min(NBINS - 1, idx));
            atomicAdd(&sh[j * NBINS + idx], 1);
        }
    }
    __syncthreads();

    int* gh = &g_hist[sex][0][0];
    for (int i = threadIdx.x; i < 10 * NBINS; i += 256) {
        int v = sh[i];
        if (v) atomicAdd(&gh[i], v);
    }
}

// ---------------- finalize: JSD + combine ----------------------------------
__global__ void finalize_kernel(float* __restrict__ out, int B) {
    __shared__ double sred[256];

    double nm = (double)g_male;
    double nf = (double)B - nm;
    const double eps = 1e-12;

    double acc = 0.0;
    const int* hm = &g_hist[0][0][0];
    const int* hf = &g_hist[1][0][0];
    for (int i = threadIdx.x; i < 10 * NBINS; i += 256) {
        double m = (double)hm[i] / nm;
        double f = (double)hf[i] / nf;
        double mid = 0.5 * (m + f);
        if (m > 0.0) acc += m * log((m + eps) / (mid + eps));
        if (f > 0.0) acc += f * log((f + eps) / (mid + eps));
    }
    sred[threadIdx.x] = acc;
    __syncthreads();
#pragma unroll
    for (int s = 128; s; s >>= 1) {
        if (threadIdx.x < s) sred[threadIdx.x] += sred[threadIdx.x + s];
        __syncthreads();
    }

    if (threadIdx.x == 0) {
        double kld = 0.5 * sred[0];
        double mse = g_mse / (double)B;
        double ce  = g_ce  / (double)B;
        out[0] = (float)((1.0 - RATIO_JSD) * (mse + ce) + RATIO_JSD * kld);
        out[1] = (float)mse;
        out[2] = (float)ce;
        out[3] = (float)(RATIO_JSD * kld);
    }
}

// ---------------- launch ----------------------------------------------------
extern "C" void kernel_launch(void* const* d_in, const int* in_sizes, int n_in,
                              void* d_out, int out_size) {
    const float* enc = (const float*)d_in[0];   // [B,11]
    const float* dec = (const float*)d_in[1];   // [B,168]
    const float* tru = (const float*)d_in[2];   // [B,168]
    const float* lab = (const float*)d_in[3];   // [B,1]
    int B = in_sizes[3];

    init_kernel<<<16, 256>>>();

    int blocks = (B + 255) / 256;
    main_kernel<<<blocks, 256>>>(enc, dec, tru, lab, B);

    dim3 hgrid(64, 2, 1);
    hist_kernel<<<hgrid, 256>>>(enc, lab, B);

    finalize_kernel<<<1, 256>>>((float*)d_out, B);
}

// round 4
// speedup vs baseline: 3.1507x; 3.1507x over previous
#include <cuda_runtime.h>

// ---------------------------------------------------------------------------
// MultiLoss_JSD: fused MSE + 17-head CE + histogram JSD
// B = 262144 rows; decoded/true: [B,168] f32; encoded: [B,11] f32; label: [B,1] f32
// out: 4 floats [multi, mse, ce, 0.1*kld]
// ---------------------------------------------------------------------------

#define NSLICE 17
#define NBINS  800
#define NCOLS  168
#define RATIO_JSD 0.1

// Compile-time column -> CE-slice classification.
__host__ __device__ constexpr int slice_of(int c) {
    const int S[NSLICE][2] = {
        {1,10},{12,29},{30,33},{33,40},{40,64},{64,79},{79,84},{84,94},{94,96},
        {96,99},{99,105},{105,113},{116,122},{122,128},{128,151},{151,159},{160,165}};
    for (int i = 0; i < NSLICE; i++)
        if (c >= S[i][0] && c < S[i][1]) return i;
    return -1;  // MSE column
}

// ---------------- scratch (device globals; no allocation allowed) ----------
__device__ double   g_mse;
__device__ double   g_ce;
__device__ unsigned g_min[10];
__device__ unsigned g_max[10];
__device__ int      g_male;
__device__ int      g_hist[2][10][NBINS];   // [sex][dim][bin]

// ordered-uint encoding of float for atomicMin/Max
__device__ __forceinline__ unsigned f2o(float f) {
    unsigned u = __float_as_uint(f);
    return (u & 0x80000000u) ? ~u : (u | 0x80000000u);
}
__device__ __forceinline__ float o2f(unsigned u) {
    return (u & 0x80000000u) ? __uint_as_float(u & 0x7FFFFFFFu)
                             : __uint_as_float(~u);
}

// ---------------- init: zero scratch ---------------------------------------
__global__ void init_kernel() {
    int tid = blockIdx.x * blockDim.x + threadIdx.x;
    int total = 2 * 10 * NBINS;
    int* h = (int*)g_hist;
    for (int i = tid; i < total; i += gridDim.x * blockDim.x) h[i] = 0;
    if (tid < 10) { g_min[tid] = 0xFFFFFFFFu; g_max[tid] = 0u; }
    if (tid == 0) { g_mse = 0.0; g_ce = 0.0; g_male = 0; }
}

// ---------------- compile-time unrolled column handling --------------------
template <int C>
__device__ __forceinline__ void handle_col(float d, float t,
                                           float (&se)[NSLICE],
                                           float& dlab, float& msea) {
    constexpr int s = slice_of(C);
    if constexpr (s >= 0) {
        se[s] += __expf(d);
        dlab = __fmaf_rn(d, t, dlab);   // t is exact one-hot 0/1
    } else {
        float diff = d - t;
        msea = __fmaf_rn(diff, diff, msea);
    }
}

template <int I>
__device__ __forceinline__ void cols_loop(const float4* __restrict__ dp,
                                          const float4* __restrict__ tp,
                                          float (&se)[NSLICE],
                                          float& dlab, float& msea) {
    if constexpr (I < NCOLS / 4) {
        float4 d = __ldg(dp + I);
        float4 t = __ldg(tp + I);
        handle_col<4 * I + 0>(d.x, t.x, se, dlab, msea);
        handle_col<4 * I + 1>(d.y, t.y, se, dlab, msea);
        handle_col<4 * I + 2>(d.z, t.z, se, dlab, msea);
        handle_col<4 * I + 3>(d.w, t.w, se, dlab, msea);
        cols_loop<I + 1>(dp, tp, se, dlab, msea);
    }
}

// ---------------- main pass: MSE + CE + minmax + male count ----------------
__global__ void __launch_bounds__(256) main_kernel(
    const float* __restrict__ enc, const float* __restrict__ dec,
    const float* __restrict__ tru, const float* __restrict__ lab, int B) {

    __shared__ float    s_ce[8], s_mse[8];
    __shared__ unsigned s_mn[10], s_mx[10];
    __shared__ int      s_male;

    int tid = threadIdx.x;
    if (tid < 10) { s_mn[tid] = 0xFFFFFFFFu; s_mx[tid] = 0u; }
    if (tid == 0) s_male = 0;
    __syncthreads();

    int row = blockIdx.x * blockDim.x + tid;

    float ce_row = 0.0f, msea = 0.0f;
    float emn[10], emx[10];
    bool is_male = false;

    if (row < B) {
        float se[NSLICE];
#pragma unroll
        for (int i = 0; i < NSLICE; i++) se[i] = 0.0f;
        float dlab = 0.0f;

        const float4* dp = (const float4*)(dec + (size_t)row * NCOLS);
        const float4* tp = (const float4*)(tru + (size_t)row * NCOLS);
        cols_loop<0>(dp, tp, se, dlab, msea);

#pragma unroll
        for (int i = 0; i < NSLICE; i++) ce_row += __logf(se[i]);
        ce_row -= dlab;

        const float* ep = enc + (size_t)row * 11;
#pragma unroll
        for (int j = 0; j < 10; j++) {
            float v = __ldg(ep + j);
            emn[j] = v; emx[j] = v;
        }
        float lv = __ldg(lab + row);
        is_male = (lv < 0.5f);
    } else {
#pragma unroll
        for (int j = 0; j < 10; j++) {
            emn[j] = __int_as_float(0x7F800000);   // +inf
            emx[j] = __int_as_float(0xFF800000);   // -inf
        }
    }

    // warp reductions
    float cer = ce_row, mser = msea;
#pragma unroll
    for (int o = 16; o; o >>= 1) {
        cer  += __shfl_xor_sync(0xFFFFFFFFu, cer,  o);
        mser += __shfl_xor_sync(0xFFFFFFFFu, mser, o);
    }
#pragma unroll
    for (int j = 0; j < 10; j++) {
        float mn = emn[j], mx = emx[j];
#pragma unroll
        for (int o = 16; o; o >>= 1) {
            mn = fminf(mn, __shfl_xor_sync(0xFFFFFFFFu, mn, o));
            mx = fmaxf(mx, __shfl_xor_sync(0xFFFFFFFFu, mx, o));
        }
        emn[j] = mn; emx[j] = mx;
    }
    unsigned mb = __ballot_sync(0xFFFFFFFFu, is_male);

    int wid = tid >> 5;
    int lid = tid & 31;
    if (lid == 0) {
        s_ce[wid]  = cer;
        s_mse[wid] = mser;
#pragma unroll
        for (int j = 0; j < 10; j++) {
            atomicMin(&s_mn[j], f2o(emn[j]));
            atomicMax(&s_mx[j], f2o(emx[j]));
        }
        atomicAdd(&s_male, __popc(mb));
    }
    __syncthreads();

    if (tid == 0) {
        float c = 0.0f, m = 0.0f;
#pragma unroll
        for (int w = 0; w < 8; w++) { c += s_ce[w]; m += s_mse[w]; }
        atomicAdd(&g_ce,  (double)c);
        atomicAdd(&g_mse, (double)m);
        atomicAdd(&g_male, s_male);
    }
    if (tid < 10) {
        atomicMin(&g_min[tid], s_mn[tid]);
        atomicMax(&g_max[tid], s_mx[tid]);
    }
}

// ---------------- histogram pass (one sex per blockIdx.y) ------------------
__global__ void __launch_bounds__(256) hist_kernel(
    const float* __restrict__ enc, const float* __restrict__ lab, int B) {

    __shared__ int sh[10 * NBINS];   // 32 KB
    for (int i = threadIdx.x; i < 10 * NBINS; i += 256) sh[i] = 0;
    __syncthreads();

    int sex = blockIdx.y;   // 0 = male (label 0), 1 = female (label 1)

    float mnv[10], rng[10];
#pragma unroll
    for (int j = 0; j < 10; j++) {
        mnv[j] = o2f(g_min[j]);
        rng[j] = o2f(g_max[j]) - mnv[j];
    }

    int stride = gridDim.x * blockDim.x;
    for (int row = blockIdx.x * blockDim.x + threadIdx.x; row < B; row += stride) {
        float lv = __ldg(lab + row);
        int rsex = (lv < 0.5f) ? 0 : 1;
        if (rsex != sex) continue;
        const float* ep = enc + (size_t)row * 11;
#pragma unroll
        for (int j = 0; j < 10; j++) {
            float x = __ldg(ep + j);
            // match jax fp32: t = (x-mn)/(mx-mn); idx = clip(floor(t*800),0,799)
            float t  = __fdiv_rn(x - mnv[j], rng[j]);
            float ft = floorf(__fmul_rn(t, (float)NBINS));
            int idx = (int)ft;
            idx = max(0, min(NBINS - 1, idx));
            atomicAdd(&sh[j * NBINS + idx], 1);
        }
    }
    __syncthreads();

    int* gh = &g_hist[sex][0][0];
    for (int i = threadIdx.x; i < 10 * NBINS; i += 256) {
        int v = sh[i];
        if (v) atomicAdd(&gh[i], v);
    }
}

// ---------------- finalize: JSD + combine (fp32 logs, matches jax f32) -----
__global__ void __launch_bounds__(1024) finalize_kernel(float* __restrict__ out, int B) {
    __shared__ double sred[32];

    float nm_inv = 1.0f / (float)g_male;
    float nf_inv = 1.0f / (float)(B - g_male);
    const float eps = 1e-12f;

    float acc = 0.0f;
    const int* hm = &g_hist[0][0][0];
    const int* hf = &g_hist[1][0][0];
    for (int i = threadIdx.x; i < 10 * NBINS; i += 1024) {
        float m = (float)hm[i] * nm_inv;
        float f = (float)hf[i] * nf_inv;
        float mid = 0.5f * (m + f);
        float inv_mid = 1.0f / (mid + eps);
        if (m > 0.0f) acc += m * logf((m + eps) * inv_mid);
        if (f > 0.0f) acc += f * logf((f + eps) * inv_mid);
    }

    // warp reduce in double (cheap: ~5 DADDs per lane)
    double d = (double)acc;
#pragma unroll
    for (int o = 16; o; o >>= 1)
        d += __shfl_xor_sync(0xFFFFFFFFu, d, o);

    int wid = threadIdx.x >> 5;
    if ((threadIdx.x & 31) == 0) sred[wid] = d;
    __syncthreads();

    if (threadIdx.x == 0) {
        double s = 0.0;
#pragma unroll
        for (int w = 0; w < 32; w++) s += sred[w];
        double kld = 0.5 * s;
        double mse = g_mse / (double)B;
        double ce  = g_ce  / (double)B;
        out[0] = (float)((1.0 - RATIO_JSD) * (mse + ce) + RATIO_JSD * kld);
        out[1] = (float)mse;
        out[2] = (float)ce;
        out[3] = (float)(RATIO_JSD * kld);
    }
}

// ---------------- launch ----------------------------------------------------
extern "C" void kernel_launch(void* const* d_in, const int* in_sizes, int n_in,
                              void* d_out, int out_size) {
    const float* enc = (const float*)d_in[0];   // [B,11]
    const float* dec = (const float*)d_in[1];   // [B,168]
    const float* tru = (const float*)d_in[2];   // [B,168]
    const float* lab = (const float*)d_in[3];   // [B,1]
    int B = in_sizes[3];

    init_kernel<<<16, 256>>>();

    int blocks = (B + 255) / 256;
    main_kernel<<<blocks, 256>>>(enc, dec, tru, lab, B);

    dim3 hgrid(128, 2, 1);
    hist_kernel<<<hgrid, 256>>>(enc, lab, B);

    finalize_kernel<<<1, 1024>>>((float*)d_out, B);
}